// round 1
// baseline (speedup 1.0000x reference)
#include <cuda_runtime.h>
#include <math.h>

#define HIDDEN 1024
#define NH     16
#define HD     64
#define SEQ    2048
#define BATCH  2
#define MTOT   (BATCH*SEQ)   // 4096
#define WIN    128           // half-window
#define QB     64
#define KT     (QB + 2*WIN)  // 320 keys in smem per query block

// ---------------- scratch (device globals; no allocation allowed) -------------
__device__ float g_Q[BATCH*NH*SEQ*HD];
__device__ float g_K[BATCH*NH*SEQ*HD];
__device__ float g_V[BATCH*NH*SEQ*HD];
__device__ float g_O[MTOT*HIDDEN];

// ---------------- SGEMM: out = A[4096,1024] @ W[1024,1024] + bias -------------
// mode 0: write [B,H,S,D] layout; mode 1: plain row-major [M,HIDDEN]
__global__ __launch_bounds__(256) void sgemm_kernel(
    const float* __restrict__ A, const float* __restrict__ W,
    const float* __restrict__ bias, float* __restrict__ out, int mode)
{
    __shared__ float As[8*128];
    __shared__ float Bs[8*128];

    const int tid = threadIdx.x;
    const int n0  = blockIdx.x * 128;
    const int m0  = blockIdx.y * 128;
    const int tx  = tid & 15;
    const int ty  = tid >> 4;

    float c[8][8];
#pragma unroll
    for (int i = 0; i < 8; i++)
#pragma unroll
        for (int j = 0; j < 8; j++) c[i][j] = 0.f;

    const int arow = tid >> 1;          // 0..127
    const int akq  = (tid & 1) * 4;     // 0 or 4
    const int brow = tid >> 5;          // 0..7
    const int bcol = (tid & 31) * 4;    // 0..124

    const float* Aptr = A + (long)(m0 + arow) * HIDDEN + akq;
    const float* Wptr = W + (long)brow * HIDDEN + n0 + bcol;

    for (int k0 = 0; k0 < HIDDEN; k0 += 8) {
        float4 av = *(const float4*)Aptr;
        float4 bw = *(const float4*)Wptr;
        As[(akq + 0) * 128 + arow] = av.x;
        As[(akq + 1) * 128 + arow] = av.y;
        As[(akq + 2) * 128 + arow] = av.z;
        As[(akq + 3) * 128 + arow] = av.w;
        *(float4*)&Bs[brow * 128 + bcol] = bw;
        __syncthreads();

#pragma unroll
        for (int k = 0; k < 8; k++) {
            float a[8], b[8];
            *(float4*)(a)     = *(const float4*)&As[k * 128 + ty * 8];
            *(float4*)(a + 4) = *(const float4*)&As[k * 128 + ty * 8 + 4];
            *(float4*)(b)     = *(const float4*)&Bs[k * 128 + tx * 8];
            *(float4*)(b + 4) = *(const float4*)&Bs[k * 128 + tx * 8 + 4];
#pragma unroll
            for (int i = 0; i < 8; i++)
#pragma unroll
                for (int j = 0; j < 8; j++)
                    c[i][j] = fmaf(a[i], b[j], c[i][j]);
        }
        __syncthreads();
        Aptr += 8;
        Wptr += 8 * HIDDEN;
    }

    float bv[8];
#pragma unroll
    for (int j = 0; j < 8; j++) bv[j] = bias[n0 + tx * 8 + j];

    if (mode == 0) {
#pragma unroll
        for (int i = 0; i < 8; i++) {
            int row = m0 + ty * 8 + i;
            int bb = row >> 11;          // / SEQ
            int s  = row & (SEQ - 1);
#pragma unroll
            for (int jq = 0; jq < 8; jq += 4) {
                int col = n0 + tx * 8 + jq;
                int hh = col >> 6;
                int d  = col & 63;
                float4 v;
                v.x = c[i][jq + 0] + bv[jq + 0];
                v.y = c[i][jq + 1] + bv[jq + 1];
                v.z = c[i][jq + 2] + bv[jq + 2];
                v.w = c[i][jq + 3] + bv[jq + 3];
                *(float4*)&out[(((long)(bb * NH + hh) * SEQ) + s) * HD + d] = v;
            }
        }
    } else {
#pragma unroll
        for (int i = 0; i < 8; i++) {
            int row = m0 + ty * 8 + i;
#pragma unroll
            for (int jq = 0; jq < 8; jq += 4) {
                int col = n0 + tx * 8 + jq;
                float4 v;
                v.x = c[i][jq + 0] + bv[jq + 0];
                v.y = c[i][jq + 1] + bv[jq + 1];
                v.z = c[i][jq + 2] + bv[jq + 2];
                v.w = c[i][jq + 3] + bv[jq + 3];
                *(float4*)&out[(long)row * HIDDEN + col] = v;
            }
        }
    }
}

// ---------------- sliding-window attention -----------------------------------
// grid (SEQ/QB, NH, BATCH), 256 threads. Full 320-key window in smem.
#define KST_STRIDE 321
#define SMEM_FLOATS (64*KST_STRIDE + KT*HD + 8*2*KT)
#define SMEM_BYTES  (SMEM_FLOATS * 4)

__global__ __launch_bounds__(256, 1) void attn_kernel(
    const float* __restrict__ Q, const float* __restrict__ K,
    const float* __restrict__ V, float* __restrict__ O)
{
    extern __shared__ float sm[];
    float* Kst  = sm;                       // [64][321]  (d-major, transposed)
    float* Vs   = sm + 64 * KST_STRIDE;     // [320][64]
    float* pbuf = Vs + KT * HD;             // [8 warps][2 queries][320]

    const int q0 = blockIdx.x * QB;
    const int h  = blockIdx.y;
    const int b  = blockIdx.z;
    const int tid = threadIdx.x;
    const long base = ((long)(b * NH + h)) * SEQ * HD;
    const float* Kb = K + base;
    const float* Vb = V + base;
    const float* Qb = Q + base;
    const int j0 = q0 - WIN;

    // load K (transposed) and V window, zero-fill out-of-range rows
    for (int idx = tid; idx < KT * 16; idx += 256) {
        int jj = idx >> 4;
        int dq = (idx & 15) << 2;
        int j  = j0 + jj;
        float4 kv = make_float4(0.f, 0.f, 0.f, 0.f);
        float4 vv = kv;
        if (j >= 0 && j < SEQ) {
            kv = *(const float4*)&Kb[(long)j * HD + dq];
            vv = *(const float4*)&Vb[(long)j * HD + dq];
        }
        Kst[(dq + 0) * KST_STRIDE + jj] = kv.x;
        Kst[(dq + 1) * KST_STRIDE + jj] = kv.y;
        Kst[(dq + 2) * KST_STRIDE + jj] = kv.z;
        Kst[(dq + 3) * KST_STRIDE + jj] = kv.w;
        *(float4*)&Vs[jj * HD + dq] = vv;
    }
    __syncthreads();

    const int w = tid >> 5;
    const int lane = tid & 31;
    float* pA = pbuf + (w * 2 + 0) * KT;
    float* pB = pbuf + (w * 2 + 1) * KT;
    const float scale = 0.125f;  // 1/sqrt(64)

    for (int rp = 0; rp < 4; rp++) {
        const int qA_ = q0 + w * 8 + rp * 2;
        const int qB_ = qA_ + 1;

        float qa[HD], qb[HD];
        const float* qpa = Qb + (long)qA_ * HD;
        const float* qpb = Qb + (long)qB_ * HD;
#pragma unroll
        for (int d = 0; d < HD; d++) { qa[d] = qpa[d]; qb[d] = qpb[d]; }

        float sA[10], sB[10];
#pragma unroll
        for (int g = 0; g < 10; g++) { sA[g] = 0.f; sB[g] = 0.f; }

        // QK^T: lanes over keys (2 queries amortize each K smem read)
#pragma unroll
        for (int d = 0; d < HD; d++) {
#pragma unroll
            for (int g = 0; g < 10; g++) {
                float kv = Kst[d * KST_STRIDE + g * 32 + lane];
                sA[g] = fmaf(qa[d], kv, sA[g]);
                sB[g] = fmaf(qb[d], kv, sB[g]);
            }
        }

        // mask + softmax
        const int jloA = (qA_ - WIN > 0 ? qA_ - WIN : 0) - j0;
        const int jhiA = (qA_ + WIN < SEQ - 1 ? qA_ + WIN : SEQ - 1) - j0;
        const int jloB = (qB_ - WIN > 0 ? qB_ - WIN : 0) - j0;
        const int jhiB = (qB_ + WIN < SEQ - 1 ? qB_ + WIN : SEQ - 1) - j0;

        float mA = -1e30f, mB = -1e30f;
#pragma unroll
        for (int g = 0; g < 10; g++) {
            int jj = g * 32 + lane;
            float sa = (jj >= jloA && jj <= jhiA) ? sA[g] * scale : -1e30f;
            float sb = (jj >= jloB && jj <= jhiB) ? sB[g] * scale : -1e30f;
            sA[g] = sa; sB[g] = sb;
            mA = fmaxf(mA, sa); mB = fmaxf(mB, sb);
        }
#pragma unroll
        for (int o = 16; o > 0; o >>= 1) {
            mA = fmaxf(mA, __shfl_xor_sync(0xffffffffu, mA, o));
            mB = fmaxf(mB, __shfl_xor_sync(0xffffffffu, mB, o));
        }
        float lA = 0.f, lB = 0.f;
#pragma unroll
        for (int g = 0; g < 10; g++) {
            float pa = __expf(sA[g] - mA);
            float pb = __expf(sB[g] - mB);
            lA += pa; lB += pb;
            pA[g * 32 + lane] = pa;
            pB[g * 32 + lane] = pb;
        }
#pragma unroll
        for (int o = 16; o > 0; o >>= 1) {
            lA += __shfl_xor_sync(0xffffffffu, lA, o);
            lB += __shfl_xor_sync(0xffffffffu, lB, o);
        }
        __syncwarp();

        // P @ V : lanes over d (lane, lane+32), float4 prob broadcasts
        float a0 = 0.f, a1 = 0.f, b0 = 0.f, b1 = 0.f;
#pragma unroll 2
        for (int jj = 0; jj < KT; jj += 4) {
            float4 p4a = *(const float4*)&pA[jj];
            float4 p4b = *(const float4*)&pB[jj];
            {
                float v0 = Vs[(jj + 0) * HD + lane];
                float v1 = Vs[(jj + 0) * HD + lane + 32];
                a0 = fmaf(p4a.x, v0, a0); a1 = fmaf(p4a.x, v1, a1);
                b0 = fmaf(p4b.x, v0, b0); b1 = fmaf(p4b.x, v1, b1);
            }
            {
                float v0 = Vs[(jj + 1) * HD + lane];
                float v1 = Vs[(jj + 1) * HD + lane + 32];
                a0 = fmaf(p4a.y, v0, a0); a1 = fmaf(p4a.y, v1, a1);
                b0 = fmaf(p4b.y, v0, b0); b1 = fmaf(p4b.y, v1, b1);
            }
            {
                float v0 = Vs[(jj + 2) * HD + lane];
                float v1 = Vs[(jj + 2) * HD + lane + 32];
                a0 = fmaf(p4a.z, v0, a0); a1 = fmaf(p4a.z, v1, a1);
                b0 = fmaf(p4b.z, v0, b0); b1 = fmaf(p4b.z, v1, b1);
            }
            {
                float v0 = Vs[(jj + 3) * HD + lane];
                float v1 = Vs[(jj + 3) * HD + lane + 32];
                a0 = fmaf(p4a.w, v0, a0); a1 = fmaf(p4a.w, v1, a1);
                b0 = fmaf(p4b.w, v0, b0); b1 = fmaf(p4b.w, v1, b1);
            }
        }

        float invA = 1.f / lA, invB = 1.f / lB;
        long obase = ((long)(b * SEQ + qA_)) * HIDDEN + h * HD;
        O[obase + lane]               = a0 * invA;
        O[obase + lane + 32]          = a1 * invA;
        O[obase + HIDDEN + lane]      = b0 * invB;
        O[obase + HIDDEN + lane + 32] = b1 * invB;
        __syncwarp();
    }
}

// ---------------- launcher -----------------------------------------------------
extern "C" void kernel_launch(void* const* d_in, const int* in_sizes, int n_in,
                              void* d_out, int out_size)
{
    const float* x  = (const float*)d_in[0];
    const float* wq = (const float*)d_in[1];
    const float* bq = (const float*)d_in[2];
    const float* wk = (const float*)d_in[3];
    const float* bk = (const float*)d_in[4];
    const float* wv = (const float*)d_in[5];
    const float* bv = (const float*)d_in[6];
    const float* wo = (const float*)d_in[7];
    const float* bo = (const float*)d_in[8];

    float *gq, *gk, *gv, *go;
    cudaGetSymbolAddress((void**)&gq, g_Q);
    cudaGetSymbolAddress((void**)&gk, g_K);
    cudaGetSymbolAddress((void**)&gv, g_V);
    cudaGetSymbolAddress((void**)&go, g_O);

    cudaFuncSetAttribute(attn_kernel,
                         cudaFuncAttributeMaxDynamicSharedMemorySize, SMEM_BYTES);

    dim3 gg(HIDDEN / 128, MTOT / 128);
    sgemm_kernel<<<gg, 256>>>(x, wq, bq, gq, 0);
    sgemm_kernel<<<gg, 256>>>(x, wk, bk, gk, 0);
    sgemm_kernel<<<gg, 256>>>(x, wv, bv, gv, 0);

    dim3 ga(SEQ / QB, NH, BATCH);
    attn_kernel<<<ga, 256, SMEM_BYTES>>>(gq, gk, gv, go);

    sgemm_kernel<<<gg, 256>>>(go, wo, bo, (float*)d_out, 1);
}

// round 3
// speedup vs baseline: 2.0112x; 2.0112x over previous
#include <cuda_runtime.h>
#include <cstdint>
#include <math.h>

#define HIDDEN 1024
#define NH     16
#define HD     64
#define SEQ    2048
#define BATCH  2
#define MTOT   (BATCH*SEQ)   // 4096
#define WIN    128
#define QB     64
#define KT     (QB + 2*WIN)  // 320

// ---------------- scratch (device globals) -------------------------------------
__device__ float g_Q[BATCH*NH*SEQ*HD];
__device__ float g_K[BATCH*NH*SEQ*HD];
__device__ float g_V[BATCH*NH*SEQ*HD];
__device__ float g_O[MTOT*HIDDEN];
__device__ float g_At[MTOT*HIDDEN];     // tf32-rounded activations
__device__ float g_Wq[HIDDEN*HIDDEN];   // tf32-rounded weights (original layout)
__device__ float g_Wk[HIDDEN*HIDDEN];
__device__ float g_Wv[HIDDEN*HIDDEN];
__device__ float g_Wo[HIDDEN*HIDDEN];

// ---------------- helpers -------------------------------------------------------
__device__ __forceinline__ uint32_t smem_u32(const void* p) {
    uint32_t a;
    asm("{ .reg .u64 t; cvta.to.shared.u64 t, %1; cvt.u32.u64 %0, t; }" : "=r"(a) : "l"(p));
    return a;
}
__device__ __forceinline__ float tf32r(float x) {
    uint32_t y;
    asm("cvt.rna.tf32.f32 %0, %1;" : "=r"(y) : "f"(x));
    return __uint_as_float(y);
}
__device__ __forceinline__ void cp16(uint32_t dst, const float* src) {
    asm volatile("cp.async.cg.shared.global [%0], [%1], 16;" :: "r"(dst), "l"(src) : "memory");
}
#define CP_COMMIT() asm volatile("cp.async.commit_group;" ::: "memory")
#define CP_WAIT2()  asm volatile("cp.async.wait_group 2;" ::: "memory")

__device__ __forceinline__ void mma_tf32(float* d, const uint32_t* a, const uint32_t* b) {
    asm volatile("mma.sync.aligned.m16n8k8.row.col.f32.tf32.tf32.f32 "
        "{%0,%1,%2,%3}, {%4,%5,%6,%7}, {%8,%9}, {%0,%1,%2,%3};"
        : "+f"(d[0]), "+f"(d[1]), "+f"(d[2]), "+f"(d[3])
        : "r"(a[0]), "r"(a[1]), "r"(a[2]), "r"(a[3]), "r"(b[0]), "r"(b[1]));
}

// ---------------- tf32 tensor-core GEMM -----------------------------------------
// out[M,N] = A[M,K] @ W[K,N] + bias ; A row-major, W row-major (K-major = mma col for B)
#define BM 128
#define BN 128
#define BK 32
#define STAGES 4
#define AS_STRIDE 36
#define BS_STRIDE 132
#define A_STAGE (BM*AS_STRIDE)             // 4608 floats
#define B_STAGE (BK*BS_STRIDE)             // 4224 floats
#define STAGE_FLOATS (A_STAGE + B_STAGE)   // 8832
#define GEMM_SMEM (STAGES*STAGE_FLOATS*4)  // 141312 B

__global__ __launch_bounds__(256, 1) void gemm_mma_kernel(
    const float* __restrict__ A,
    const float* __restrict__ W0, const float* __restrict__ W1, const float* __restrict__ W2,
    const float* __restrict__ bias0, const float* __restrict__ bias1, const float* __restrict__ bias2,
    float* __restrict__ out0, float* __restrict__ out1, float* __restrict__ out2,
    int mode)
{
    extern __shared__ float sm[];
    const int tid  = threadIdx.x;
    const int lane = tid & 31;
    const int wid  = tid >> 5;
    const int n0 = blockIdx.x * BN;
    const int m0 = blockIdx.y * BM;
    const int z  = blockIdx.z;

    const float* W    = (z == 0) ? W0 : (z == 1) ? W1 : W2;
    const float* bias = (z == 0) ? bias0 : (z == 1) ? bias1 : bias2;
    float* out        = (z == 0) ? out0 : (z == 1) ? out1 : out2;

    const int wm = (wid & 1) * 64;
    const int wn = (wid >> 1) * 32;

    float d[4][4][4];
#pragma unroll
    for (int mi = 0; mi < 4; mi++)
#pragma unroll
        for (int ni = 0; ni < 4; ni++)
#pragma unroll
            for (int c = 0; c < 4; c++) d[mi][ni][c] = 0.f;

    const uint32_t sb = smem_u32(sm);

    // ---- stage loader: A[128][36] row-major; B[32][132] k-major ----
    auto load_stage = [&](int kt, int s) {
        const uint32_t a_off = sb + (uint32_t)(s * STAGE_FLOATS) * 4u;
        const uint32_t b_off = a_off + A_STAGE * 4u;
        const float* Ag = A + (long)m0 * HIDDEN + kt * BK;
        const float* Wg = W + (long)(kt * BK) * HIDDEN + n0;
#pragma unroll
        for (int rep = 0; rep < 4; rep++) {
            int lin = rep * 256 + tid;
            int ar = lin >> 3, aq = lin & 7;
            cp16(a_off + (uint32_t)(ar * AS_STRIDE + aq * 4) * 4u,
                 Ag + (long)ar * HIDDEN + aq * 4);
            int br = lin >> 5, bq = lin & 31;
            cp16(b_off + (uint32_t)(br * BS_STRIDE + bq * 4) * 4u,
                 Wg + (long)br * HIDDEN + bq * 4);
        }
        CP_COMMIT();
    };

#pragma unroll
    for (int p = 0; p < 3; p++) load_stage(p, p);

    const int lg = lane >> 2;   // group id 0..7
    const int lt = lane & 3;    // thread-in-group 0..3

    for (int kt = 0; kt < HIDDEN / BK; kt++) {
        const int s = kt & (STAGES - 1);
        CP_WAIT2();
        __syncthreads();
        if (kt + 3 < HIDDEN / BK) load_stage(kt + 3, (kt + 3) & (STAGES - 1));
        else CP_COMMIT();   // keep group accounting constant

        const float* As = sm + s * STAGE_FLOATS;
        const float* Bs = As + A_STAGE;

#pragma unroll
        for (int k8 = 0; k8 < 4; k8++) {
            const int kb = k8 * 8;
            uint32_t a[4][4], b[4][2];
#pragma unroll
            for (int mi = 0; mi < 4; mi++) {
                const float* ap = As + (wm + mi * 16 + lg) * AS_STRIDE + kb + lt;
                a[mi][0] = __float_as_uint(ap[0]);
                a[mi][1] = __float_as_uint(ap[8 * AS_STRIDE]);
                a[mi][2] = __float_as_uint(ap[4]);
                a[mi][3] = __float_as_uint(ap[8 * AS_STRIDE + 4]);
            }
#pragma unroll
            for (int ni = 0; ni < 4; ni++) {
                const float* bp = Bs + (kb + lt) * BS_STRIDE + wn + ni * 8 + lg;
                b[ni][0] = __float_as_uint(bp[0]);
                b[ni][1] = __float_as_uint(bp[4 * BS_STRIDE]);
            }
#pragma unroll
            for (int mi = 0; mi < 4; mi++)
#pragma unroll
                for (int ni = 0; ni < 4; ni++)
                    mma_tf32(d[mi][ni], a[mi], b[ni]);
        }
    }

    // ---- epilogue ----
#pragma unroll
    for (int mi = 0; mi < 4; mi++) {
#pragma unroll
        for (int rh = 0; rh < 2; rh++) {
            const int row = m0 + wm + mi * 16 + lg + rh * 8;
            const int bb = row >> 11;
            const int ss = row & (SEQ - 1);
#pragma unroll
            for (int ni = 0; ni < 4; ni++) {
                const int col = n0 + wn + ni * 8 + lt * 2;
                float2 v;
                v.x = d[mi][ni][rh * 2 + 0] + __ldg(&bias[col]);
                v.y = d[mi][ni][rh * 2 + 1] + __ldg(&bias[col + 1]);
                if (mode == 0) {
                    const int h  = col >> 6;
                    const int dd = col & 63;
                    *(float2*)&out[(((long)(bb * NH + h) * SEQ) + ss) * HD + dd] = v;
                } else {
                    *(float2*)&out[(long)row * HIDDEN + col] = v;
                }
            }
        }
    }
}

// ---------------- tf32 rounding (elementwise) ------------------------------------
__global__ void cvt_kernel(const float4* __restrict__ in, float4* __restrict__ out, int n4) {
    int i = blockIdx.x * blockDim.x + threadIdx.x;
    if (i < n4) {
        float4 v = in[i];
        v.x = tf32r(v.x); v.y = tf32r(v.y); v.z = tf32r(v.z); v.w = tf32r(v.w);
        out[i] = v;
    }
}

// ---------------- sliding-window attention (unchanged from R1) -------------------
#define KST_STRIDE 321
#define SMEM_FLOATS (64*KST_STRIDE + KT*HD + 8*2*KT)
#define SMEM_BYTES  (SMEM_FLOATS * 4)

__global__ __launch_bounds__(256, 1) void attn_kernel(
    const float* __restrict__ Q, const float* __restrict__ K,
    const float* __restrict__ V, float* __restrict__ O)
{
    extern __shared__ float sm[];
    float* Kst  = sm;
    float* Vs   = sm + 64 * KST_STRIDE;
    float* pbuf = Vs + KT * HD;

    const int q0 = blockIdx.x * QB;
    const int h  = blockIdx.y;
    const int b  = blockIdx.z;
    const int tid = threadIdx.x;
    const long base = ((long)(b * NH + h)) * SEQ * HD;
    const float* Kb = K + base;
    const float* Vb = V + base;
    const float* Qb = Q + base;
    const int j0 = q0 - WIN;

    for (int idx = tid; idx < KT * 16; idx += 256) {
        int jj = idx >> 4;
        int dq = (idx & 15) << 2;
        int j  = j0 + jj;
        float4 kv = make_float4(0.f, 0.f, 0.f, 0.f);
        float4 vv = kv;
        if (j >= 0 && j < SEQ) {
            kv = *(const float4*)&Kb[(long)j * HD + dq];
            vv = *(const float4*)&Vb[(long)j * HD + dq];
        }
        Kst[(dq + 0) * KST_STRIDE + jj] = kv.x;
        Kst[(dq + 1) * KST_STRIDE + jj] = kv.y;
        Kst[(dq + 2) * KST_STRIDE + jj] = kv.z;
        Kst[(dq + 3) * KST_STRIDE + jj] = kv.w;
        *(float4*)&Vs[jj * HD + dq] = vv;
    }
    __syncthreads();

    const int w = tid >> 5;
    const int lane = tid & 31;
    float* pA = pbuf + (w * 2 + 0) * KT;
    float* pB = pbuf + (w * 2 + 1) * KT;
    const float scale = 0.125f;

    for (int rp = 0; rp < 4; rp++) {
        const int qA_ = q0 + w * 8 + rp * 2;
        const int qB_ = qA_ + 1;

        float qa[HD], qb[HD];
        const float* qpa = Qb + (long)qA_ * HD;
        const float* qpb = Qb + (long)qB_ * HD;
#pragma unroll
        for (int d = 0; d < HD; d++) { qa[d] = qpa[d]; qb[d] = qpb[d]; }

        float sA[10], sB[10];
#pragma unroll
        for (int g = 0; g < 10; g++) { sA[g] = 0.f; sB[g] = 0.f; }

#pragma unroll
        for (int d = 0; d < HD; d++) {
#pragma unroll
            for (int g = 0; g < 10; g++) {
                float kv = Kst[d * KST_STRIDE + g * 32 + lane];
                sA[g] = fmaf(qa[d], kv, sA[g]);
                sB[g] = fmaf(qb[d], kv, sB[g]);
            }
        }

        const int jloA = (qA_ - WIN > 0 ? qA_ - WIN : 0) - j0;
        const int jhiA = (qA_ + WIN < SEQ - 1 ? qA_ + WIN : SEQ - 1) - j0;
        const int jloB = (qB_ - WIN > 0 ? qB_ - WIN : 0) - j0;
        const int jhiB = (qB_ + WIN < SEQ - 1 ? qB_ + WIN : SEQ - 1) - j0;

        float mA = -1e30f, mB = -1e30f;
#pragma unroll
        for (int g = 0; g < 10; g++) {
            int jj = g * 32 + lane;
            float sa = (jj >= jloA && jj <= jhiA) ? sA[g] * scale : -1e30f;
            float sb = (jj >= jloB && jj <= jhiB) ? sB[g] * scale : -1e30f;
            sA[g] = sa; sB[g] = sb;
            mA = fmaxf(mA, sa); mB = fmaxf(mB, sb);
        }
#pragma unroll
        for (int o = 16; o > 0; o >>= 1) {
            mA = fmaxf(mA, __shfl_xor_sync(0xffffffffu, mA, o));
            mB = fmaxf(mB, __shfl_xor_sync(0xffffffffu, mB, o));
        }
        float lA = 0.f, lB = 0.f;
#pragma unroll
        for (int g = 0; g < 10; g++) {
            float pa = __expf(sA[g] - mA);
            float pb = __expf(sB[g] - mB);
            lA += pa; lB += pb;
            pA[g * 32 + lane] = pa;
            pB[g * 32 + lane] = pb;
        }
#pragma unroll
        for (int o = 16; o > 0; o >>= 1) {
            lA += __shfl_xor_sync(0xffffffffu, lA, o);
            lB += __shfl_xor_sync(0xffffffffu, lB, o);
        }
        __syncwarp();

        float a0 = 0.f, a1 = 0.f, b0 = 0.f, b1 = 0.f;
#pragma unroll 2
        for (int jj = 0; jj < KT; jj += 4) {
            float4 p4a = *(const float4*)&pA[jj];
            float4 p4b = *(const float4*)&pB[jj];
            {
                float v0 = Vs[(jj + 0) * HD + lane];
                float v1 = Vs[(jj + 0) * HD + lane + 32];
                a0 = fmaf(p4a.x, v0, a0); a1 = fmaf(p4a.x, v1, a1);
                b0 = fmaf(p4b.x, v0, b0); b1 = fmaf(p4b.x, v1, b1);
            }
            {
                float v0 = Vs[(jj + 1) * HD + lane];
                float v1 = Vs[(jj + 1) * HD + lane + 32];
                a0 = fmaf(p4a.y, v0, a0); a1 = fmaf(p4a.y, v1, a1);
                b0 = fmaf(p4b.y, v0, b0); b1 = fmaf(p4b.y, v1, b1);
            }
            {
                float v0 = Vs[(jj + 2) * HD + lane];
                float v1 = Vs[(jj + 2) * HD + lane + 32];
                a0 = fmaf(p4a.z, v0, a0); a1 = fmaf(p4a.z, v1, a1);
                b0 = fmaf(p4b.z, v0, b0); b1 = fmaf(p4b.z, v1, b1);
            }
            {
                float v0 = Vs[(jj + 3) * HD + lane];
                float v1 = Vs[(jj + 3) * HD + lane + 32];
                a0 = fmaf(p4a.w, v0, a0); a1 = fmaf(p4a.w, v1, a1);
                b0 = fmaf(p4b.w, v0, b0); b1 = fmaf(p4b.w, v1, b1);
            }
        }

        float invA = 1.f / lA, invB = 1.f / lB;
        long obase = ((long)(b * SEQ + qA_)) * HIDDEN + h * HD;
        O[obase + lane]               = a0 * invA;
        O[obase + lane + 32]          = a1 * invA;
        O[obase + HIDDEN + lane]      = b0 * invB;
        O[obase + HIDDEN + lane + 32] = b1 * invB;
        __syncwarp();
    }
}

// ---------------- launcher --------------------------------------------------------
extern "C" void kernel_launch(void* const* d_in, const int* in_sizes, int n_in,
                              void* d_out, int out_size)
{
    const float* x  = (const float*)d_in[0];
    const float* wq = (const float*)d_in[1];
    const float* bq = (const float*)d_in[2];
    const float* wk = (const float*)d_in[3];
    const float* bk = (const float*)d_in[4];
    const float* wv = (const float*)d_in[5];
    const float* bv = (const float*)d_in[6];
    const float* wo = (const float*)d_in[7];
    const float* bo = (const float*)d_in[8];

    float *gq, *gk, *gv, *go, *gat, *gwq, *gwk, *gwv, *gwo;
    cudaGetSymbolAddress((void**)&gq,  g_Q);
    cudaGetSymbolAddress((void**)&gk,  g_K);
    cudaGetSymbolAddress((void**)&gv,  g_V);
    cudaGetSymbolAddress((void**)&go,  g_O);
    cudaGetSymbolAddress((void**)&gat, g_At);
    cudaGetSymbolAddress((void**)&gwq, g_Wq);
    cudaGetSymbolAddress((void**)&gwk, g_Wk);
    cudaGetSymbolAddress((void**)&gwv, g_Wv);
    cudaGetSymbolAddress((void**)&gwo, g_Wo);

    cudaFuncSetAttribute(gemm_mma_kernel,
                         cudaFuncAttributeMaxDynamicSharedMemorySize, GEMM_SMEM);
    cudaFuncSetAttribute(attn_kernel,
                         cudaFuncAttributeMaxDynamicSharedMemorySize, SMEM_BYTES);

    const int n4a = MTOT * HIDDEN / 4;
    const int n4w = HIDDEN * HIDDEN / 4;

    // round activations + weights to tf32 (rna, unbiased)
    cvt_kernel<<<(n4a + 255) / 256, 256>>>((const float4*)x,  (float4*)gat, n4a);
    cvt_kernel<<<(n4w + 255) / 256, 256>>>((const float4*)wq, (float4*)gwq, n4w);
    cvt_kernel<<<(n4w + 255) / 256, 256>>>((const float4*)wk, (float4*)gwk, n4w);
    cvt_kernel<<<(n4w + 255) / 256, 256>>>((const float4*)wv, (float4*)gwv, n4w);
    cvt_kernel<<<(n4w + 255) / 256, 256>>>((const float4*)wo, (float4*)gwo, n4w);

    // fused QKV projections (tensor cores, tf32)
    {
        dim3 g(HIDDEN / BN, MTOT / BM, 3);
        gemm_mma_kernel<<<g, 256, GEMM_SMEM>>>(gat, gwq, gwk, gwv,
                                               bq, bk, bv, gq, gk, gv, 0);
    }
    // attention
    {
        dim3 ga(SEQ / QB, NH, BATCH);
        attn_kernel<<<ga, 256, SMEM_BYTES>>>(gq, gk, gv, go);
    }
    // round attention output, then output projection
    cvt_kernel<<<(n4a + 255) / 256, 256>>>((const float4*)go, (float4*)gat, n4a);
    {
        dim3 g(HIDDEN / BN, MTOT / BM, 1);
        gemm_mma_kernel<<<g, 256, GEMM_SMEM>>>(gat, gwo, gwo, gwo,
                                               bo, bo, bo, (float*)d_out,
                                               (float*)d_out, (float*)d_out, 1);
    }
}

// round 4
// speedup vs baseline: 2.5487x; 1.2673x over previous
#include <cuda_runtime.h>
#include <cstdint>
#include <math.h>

#define HIDDEN 1024
#define NH     16
#define HD     64
#define SEQ    2048
#define BATCH  2
#define MTOT   (BATCH*SEQ)   // 4096
#define WIN    128
#define QB     64
#define KT     (QB + 2*WIN)  // 320

// ---------------- scratch (device globals) -------------------------------------
__device__ float g_Q[BATCH*NH*SEQ*HD];
__device__ float g_K[BATCH*NH*SEQ*HD];
__device__ float g_V[BATCH*NH*SEQ*HD];
__device__ float g_At[MTOT*HIDDEN];     // tf32-rounded activations
__device__ float g_Wq[HIDDEN*HIDDEN];
__device__ float g_Wk[HIDDEN*HIDDEN];
__device__ float g_Wv[HIDDEN*HIDDEN];
__device__ float g_Wo[HIDDEN*HIDDEN];

// ---------------- helpers -------------------------------------------------------
__device__ __forceinline__ uint32_t smem_u32(const void* p) {
    uint32_t a;
    asm("{ .reg .u64 t; cvta.to.shared.u64 t, %1; cvt.u32.u64 %0, t; }" : "=r"(a) : "l"(p));
    return a;
}
__device__ __forceinline__ float tf32r(float x) {
    uint32_t y;
    asm("cvt.rna.tf32.f32 %0, %1;" : "=r"(y) : "f"(x));
    return __uint_as_float(y);
}
__device__ __forceinline__ void cp16(uint32_t dst, const float* src) {
    asm volatile("cp.async.cg.shared.global [%0], [%1], 16;" :: "r"(dst), "l"(src) : "memory");
}
#define CP_COMMIT() asm volatile("cp.async.commit_group;" ::: "memory")
#define CP_WAIT2()  asm volatile("cp.async.wait_group 2;" ::: "memory")

__device__ __forceinline__ void mma_tf32(float* d, const uint32_t* a, const uint32_t* b) {
    asm volatile("mma.sync.aligned.m16n8k8.row.col.f32.tf32.tf32.f32 "
        "{%0,%1,%2,%3}, {%4,%5,%6,%7}, {%8,%9}, {%0,%1,%2,%3};"
        : "+f"(d[0]), "+f"(d[1]), "+f"(d[2]), "+f"(d[3])
        : "r"(a[0]), "r"(a[1]), "r"(a[2]), "r"(a[3]), "r"(b[0]), "r"(b[1]));
}

// ---------------- tf32 tensor-core GEMM (unchanged from R3) ----------------------
#define BM 128
#define BN 128
#define BK 32
#define STAGES 4
#define AS_STRIDE 36
#define BS_STRIDE 132
#define A_STAGE (BM*AS_STRIDE)
#define B_STAGE (BK*BS_STRIDE)
#define STAGE_FLOATS (A_STAGE + B_STAGE)
#define GEMM_SMEM (STAGES*STAGE_FLOATS*4)

__global__ __launch_bounds__(256, 1) void gemm_mma_kernel(
    const float* __restrict__ A,
    const float* __restrict__ W0, const float* __restrict__ W1, const float* __restrict__ W2,
    const float* __restrict__ bias0, const float* __restrict__ bias1, const float* __restrict__ bias2,
    float* __restrict__ out0, float* __restrict__ out1, float* __restrict__ out2,
    int mode)
{
    extern __shared__ float sm[];
    const int tid  = threadIdx.x;
    const int lane = tid & 31;
    const int wid  = tid >> 5;
    const int n0 = blockIdx.x * BN;
    const int m0 = blockIdx.y * BM;
    const int z  = blockIdx.z;

    const float* W    = (z == 0) ? W0 : (z == 1) ? W1 : W2;
    const float* bias = (z == 0) ? bias0 : (z == 1) ? bias1 : bias2;
    float* out        = (z == 0) ? out0 : (z == 1) ? out1 : out2;

    const int wm = (wid & 1) * 64;
    const int wn = (wid >> 1) * 32;

    float d[4][4][4];
#pragma unroll
    for (int mi = 0; mi < 4; mi++)
#pragma unroll
        for (int ni = 0; ni < 4; ni++)
#pragma unroll
            for (int c = 0; c < 4; c++) d[mi][ni][c] = 0.f;

    const uint32_t sb = smem_u32(sm);

    auto load_stage = [&](int kt, int s) {
        const uint32_t a_off = sb + (uint32_t)(s * STAGE_FLOATS) * 4u;
        const uint32_t b_off = a_off + A_STAGE * 4u;
        const float* Ag = A + (long)m0 * HIDDEN + kt * BK;
        const float* Wg = W + (long)(kt * BK) * HIDDEN + n0;
#pragma unroll
        for (int rep = 0; rep < 4; rep++) {
            int lin = rep * 256 + tid;
            int ar = lin >> 3, aq = lin & 7;
            cp16(a_off + (uint32_t)(ar * AS_STRIDE + aq * 4) * 4u,
                 Ag + (long)ar * HIDDEN + aq * 4);
            int br = lin >> 5, bq = lin & 31;
            cp16(b_off + (uint32_t)(br * BS_STRIDE + bq * 4) * 4u,
                 Wg + (long)br * HIDDEN + bq * 4);
        }
        CP_COMMIT();
    };

#pragma unroll
    for (int p = 0; p < 3; p++) load_stage(p, p);

    const int lg = lane >> 2;
    const int lt = lane & 3;

    for (int kt = 0; kt < HIDDEN / BK; kt++) {
        const int s = kt & (STAGES - 1);
        CP_WAIT2();
        __syncthreads();
        if (kt + 3 < HIDDEN / BK) load_stage(kt + 3, (kt + 3) & (STAGES - 1));
        else CP_COMMIT();

        const float* As = sm + s * STAGE_FLOATS;
        const float* Bs = As + A_STAGE;

#pragma unroll
        for (int k8 = 0; k8 < 4; k8++) {
            const int kb = k8 * 8;
            uint32_t a[4][4], b[4][2];
#pragma unroll
            for (int mi = 0; mi < 4; mi++) {
                const float* ap = As + (wm + mi * 16 + lg) * AS_STRIDE + kb + lt;
                a[mi][0] = __float_as_uint(ap[0]);
                a[mi][1] = __float_as_uint(ap[8 * AS_STRIDE]);
                a[mi][2] = __float_as_uint(ap[4]);
                a[mi][3] = __float_as_uint(ap[8 * AS_STRIDE + 4]);
            }
#pragma unroll
            for (int ni = 0; ni < 4; ni++) {
                const float* bp = Bs + (kb + lt) * BS_STRIDE + wn + ni * 8 + lg;
                b[ni][0] = __float_as_uint(bp[0]);
                b[ni][1] = __float_as_uint(bp[4 * BS_STRIDE]);
            }
#pragma unroll
            for (int mi = 0; mi < 4; mi++)
#pragma unroll
                for (int ni = 0; ni < 4; ni++)
                    mma_tf32(d[mi][ni], a[mi], b[ni]);
        }
    }

#pragma unroll
    for (int mi = 0; mi < 4; mi++) {
#pragma unroll
        for (int rh = 0; rh < 2; rh++) {
            const int row = m0 + wm + mi * 16 + lg + rh * 8;
            const int bb = row >> 11;
            const int ss = row & (SEQ - 1);
#pragma unroll
            for (int ni = 0; ni < 4; ni++) {
                const int col = n0 + wn + ni * 8 + lt * 2;
                float2 v;
                v.x = d[mi][ni][rh * 2 + 0] + __ldg(&bias[col]);
                v.y = d[mi][ni][rh * 2 + 1] + __ldg(&bias[col + 1]);
                if (mode == 0) {
                    const int h  = col >> 6;
                    const int dd = col & 63;
                    *(float2*)&out[(((long)(bb * NH + h) * SEQ) + ss) * HD + dd] = v;
                } else {
                    *(float2*)&out[(long)row * HIDDEN + col] = v;
                }
            }
        }
    }
}

// ---------------- tf32 rounding (elementwise) ------------------------------------
__global__ void cvt_kernel(const float4* __restrict__ in, float4* __restrict__ out, int n4) {
    int i = blockIdx.x * blockDim.x + threadIdx.x;
    if (i < n4) {
        float4 v = in[i];
        v.x = tf32r(v.x); v.y = tf32r(v.y); v.z = tf32r(v.z); v.w = tf32r(v.w);
        out[i] = v;
    }
}

// ---------------- sliding-window attention via tensor-core MMA --------------------
// per CTA: (qblock 64, head, batch). S = Q K^T (tf32 mma), exp (no max-sub; scores
// are O(1) by construction), P@V (tf32 mma, split-K across warp pairs).
// smem strides chosen so every fragment LDS is bank-conflict-free.
#define SQ 68
#define SK 328
#define SV 72
#define SP 324
#define SO 66
#define QS_OFF  0
#define KP_OFF  4352
#define VS_OFF  (KP_OFF + 64*SK)            // 25344
#define RED_OFF (VS_OFF + KT*SV)            // 48384
#define ATTN_FLOATS (RED_OFF + 128)         // 48512
#define ATTN_SMEM (ATTN_FLOATS * 4)         // 194048 B

__global__ __launch_bounds__(256, 1) void attn_mma_kernel(
    const float* __restrict__ Q, const float* __restrict__ K,
    const float* __restrict__ V, float* __restrict__ O)
{
    extern __shared__ float sm[];
    float* Qs  = sm + QS_OFF;   // [64][68], reused as obuf [64][66]
    float* Kst = sm + KP_OFF;   // [64][328] d-major, reused as P [64][324]
    float* Vs  = sm + VS_OFF;   // [320][72]
    float* red = sm + RED_OFF;  // [2][64] row sums

    const int q0 = blockIdx.x * QB;
    const int h  = blockIdx.y;
    const int b  = blockIdx.z;
    const int tid = threadIdx.x;
    const long base = ((long)(b * NH + h)) * SEQ * HD;
    const float* Kb = K + base;
    const float* Vb = V + base;
    const float* Qb = Q + base;
    const int j0 = q0 - WIN;

    // ---- load Q tile (rounded tf32), stride 68 ----
    for (int idx = tid; idx < 64 * 16; idx += 256) {
        int r = idx >> 4, c4 = (idx & 15) << 2;
        float4 v = *(const float4*)&Qb[(long)(q0 + r) * HD + c4];
        v.x = tf32r(v.x); v.y = tf32r(v.y); v.z = tf32r(v.z); v.w = tf32r(v.w);
        *(float4*)&Qs[r * SQ + c4] = v;
    }
    // ---- load K transposed [d][key], stride 328; key-fastest for conflict-free STS
    for (int idx = tid; idx < 16 * KT; idx += 256) {
        int jj = idx % KT;
        int dq = (idx / KT) << 2;
        int j = j0 + jj;
        float4 v = make_float4(0.f, 0.f, 0.f, 0.f);
        if (j >= 0 && j < SEQ) v = *(const float4*)&Kb[(long)j * HD + dq];
        Kst[(dq + 0) * SK + jj] = tf32r(v.x);
        Kst[(dq + 1) * SK + jj] = tf32r(v.y);
        Kst[(dq + 2) * SK + jj] = tf32r(v.z);
        Kst[(dq + 3) * SK + jj] = tf32r(v.w);
    }
    // ---- load V [key][d], stride 72 ----
    for (int idx = tid; idx < KT * 16; idx += 256) {
        int jj = idx >> 4, dq = (idx & 15) << 2;
        int j = j0 + jj;
        float4 v = make_float4(0.f, 0.f, 0.f, 0.f);
        if (j >= 0 && j < SEQ) v = *(const float4*)&Vb[(long)j * HD + dq];
        v.x = tf32r(v.x); v.y = tf32r(v.y); v.z = tf32r(v.z); v.w = tf32r(v.w);
        *(float4*)&Vs[jj * SV + dq] = v;
    }
    __syncthreads();

    const int lane = tid & 31;
    const int wid  = tid >> 5;
    const int lg = lane >> 2;      // 0..7
    const int lt = lane & 3;       // 0..3
    const int wm = (wid & 3) * 16; // query tile row base
    const int wn = (wid >> 2) * 160; // key half (0 or 160)
    const float scale = 0.125f;

    // ---- S = Q @ K^T : m16 x n160 x k64 per warp ----
    uint32_t a[8][4];
#pragma unroll
    for (int k8 = 0; k8 < 8; k8++) {
        const float* ap = Qs + (wm + lg) * SQ + k8 * 8 + lt;
        a[k8][0] = __float_as_uint(ap[0]);
        a[k8][1] = __float_as_uint(ap[8 * SQ]);
        a[k8][2] = __float_as_uint(ap[4]);
        a[k8][3] = __float_as_uint(ap[8 * SQ + 4]);
    }
    float c[20][4];
#pragma unroll
    for (int nt = 0; nt < 20; nt++) {
        c[nt][0] = 0.f; c[nt][1] = 0.f; c[nt][2] = 0.f; c[nt][3] = 0.f;
        const int key = wn + nt * 8 + lg;
#pragma unroll
        for (int k8 = 0; k8 < 8; k8++) {
            uint32_t bb[2];
            const float* bp = Kst + (k8 * 8 + lt) * SK + key;
            bb[0] = __float_as_uint(bp[0]);
            bb[1] = __float_as_uint(bp[4 * SK]);
            mma_tf32(c[nt], a[k8], bb);
        }
    }

    // ---- band mask + exp (no max-sub) + row sums ----
    const int r0 = q0 + wm + lg;
    const int r1 = r0 + 8;
    const int lo0 = ((r0 - WIN > 0) ? r0 - WIN : 0) - j0;
    const int hi0 = ((r0 + WIN < SEQ - 1) ? r0 + WIN : SEQ - 1) - j0;
    const int lo1 = ((r1 - WIN > 0) ? r1 - WIN : 0) - j0;
    const int hi1 = ((r1 + WIN < SEQ - 1) ? r1 + WIN : SEQ - 1) - j0;

    float sum0 = 0.f, sum1 = 0.f;
#pragma unroll
    for (int nt = 0; nt < 20; nt++) {
        const int jj = wn + nt * 8 + 2 * lt;
        float p0 = (jj     >= lo0 && jj     <= hi0) ? tf32r(__expf(c[nt][0] * scale)) : 0.f;
        float p1 = (jj + 1 >= lo0 && jj + 1 <= hi0) ? tf32r(__expf(c[nt][1] * scale)) : 0.f;
        float p2 = (jj     >= lo1 && jj     <= hi1) ? tf32r(__expf(c[nt][2] * scale)) : 0.f;
        float p3 = (jj + 1 >= lo1 && jj + 1 <= hi1) ? tf32r(__expf(c[nt][3] * scale)) : 0.f;
        c[nt][0] = p0; c[nt][1] = p1; c[nt][2] = p2; c[nt][3] = p3;
        sum0 += p0 + p1;
        sum1 += p2 + p3;
    }
    sum0 += __shfl_xor_sync(0xffffffffu, sum0, 1);
    sum0 += __shfl_xor_sync(0xffffffffu, sum0, 2);
    sum1 += __shfl_xor_sync(0xffffffffu, sum1, 1);
    sum1 += __shfl_xor_sync(0xffffffffu, sum1, 2);

    __syncthreads();   // all warps done reading Kst; safe to overwrite with P

    float* Ps = Kst;   // alias: P [64][324]
#pragma unroll
    for (int nt = 0; nt < 20; nt++) {
        const int col = wn + nt * 8 + 2 * lt;
        *(float2*)&Ps[(wm + lg) * SP + col]     = make_float2(c[nt][0], c[nt][1]);
        *(float2*)&Ps[(wm + lg + 8) * SP + col] = make_float2(c[nt][2], c[nt][3]);
    }
    if (lt == 0) {
        red[(wid >> 2) * 64 + wm + lg]     = sum0;
        red[(wid >> 2) * 64 + wm + lg + 8] = sum1;
    }
    __syncthreads();

    // ---- O_partial = P @ V : m16 x n64 x k160 per warp (split-K pairs) ----
    float o[8][4];
#pragma unroll
    for (int nt = 0; nt < 8; nt++) { o[nt][0] = 0.f; o[nt][1] = 0.f; o[nt][2] = 0.f; o[nt][3] = 0.f; }

#pragma unroll
    for (int k8 = 0; k8 < 20; k8++) {
        const int kk = wn + k8 * 8;
        uint32_t a2[4];
        const float* ap = Ps + (wm + lg) * SP + kk + lt;
        a2[0] = __float_as_uint(ap[0]);
        a2[1] = __float_as_uint(ap[8 * SP]);
        a2[2] = __float_as_uint(ap[4]);
        a2[3] = __float_as_uint(ap[8 * SP + 4]);
#pragma unroll
        for (int nt = 0; nt < 8; nt++) {
            uint32_t bb[2];
            const float* bp = Vs + (kk + lt) * SV + nt * 8 + lg;
            bb[0] = __float_as_uint(bp[0]);
            bb[1] = __float_as_uint(bp[4 * SV]);
            mma_tf32(o[nt], a2, bb);
        }
    }

    // ---- combine split-K halves, normalize, write tf32-rounded ----
    float* obuf = Qs;  // alias [64][66]
    if ((wid >> 2) == 0) {
#pragma unroll
        for (int nt = 0; nt < 8; nt++) {
            const int col = nt * 8 + 2 * lt;
            *(float2*)&obuf[(wm + lg) * SO + col]     = make_float2(o[nt][0], o[nt][1]);
            *(float2*)&obuf[(wm + lg + 8) * SO + col] = make_float2(o[nt][2], o[nt][3]);
        }
    }
    __syncthreads();
    if ((wid >> 2) == 1) {
        const float inv0 = 1.f / (red[wm + lg] + red[64 + wm + lg]);
        const float inv1 = 1.f / (red[wm + lg + 8] + red[64 + wm + lg + 8]);
        const long ob0 = ((long)(b * SEQ + r0)) * HIDDEN + h * HD;
        const long ob1 = ((long)(b * SEQ + r1)) * HIDDEN + h * HD;
#pragma unroll
        for (int nt = 0; nt < 8; nt++) {
            const int col = nt * 8 + 2 * lt;
            float2 u0 = *(const float2*)&obuf[(wm + lg) * SO + col];
            float2 u1 = *(const float2*)&obuf[(wm + lg + 8) * SO + col];
            float2 w0, w1;
            w0.x = tf32r((o[nt][0] + u0.x) * inv0);
            w0.y = tf32r((o[nt][1] + u0.y) * inv0);
            w1.x = tf32r((o[nt][2] + u1.x) * inv1);
            w1.y = tf32r((o[nt][3] + u1.y) * inv1);
            *(float2*)&O[ob0 + col] = w0;
            *(float2*)&O[ob1 + col] = w1;
        }
    }
}

// ---------------- launcher --------------------------------------------------------
extern "C" void kernel_launch(void* const* d_in, const int* in_sizes, int n_in,
                              void* d_out, int out_size)
{
    const float* x  = (const float*)d_in[0];
    const float* wq = (const float*)d_in[1];
    const float* bq = (const float*)d_in[2];
    const float* wk = (const float*)d_in[3];
    const float* bk = (const float*)d_in[4];
    const float* wv = (const float*)d_in[5];
    const float* bv = (const float*)d_in[6];
    const float* wo = (const float*)d_in[7];
    const float* bo = (const float*)d_in[8];

    float *gq, *gk, *gv, *gat, *gwq, *gwk, *gwv, *gwo;
    cudaGetSymbolAddress((void**)&gq,  g_Q);
    cudaGetSymbolAddress((void**)&gk,  g_K);
    cudaGetSymbolAddress((void**)&gv,  g_V);
    cudaGetSymbolAddress((void**)&gat, g_At);
    cudaGetSymbolAddress((void**)&gwq, g_Wq);
    cudaGetSymbolAddress((void**)&gwk, g_Wk);
    cudaGetSymbolAddress((void**)&gwv, g_Wv);
    cudaGetSymbolAddress((void**)&gwo, g_Wo);

    cudaFuncSetAttribute(gemm_mma_kernel,
                         cudaFuncAttributeMaxDynamicSharedMemorySize, GEMM_SMEM);
    cudaFuncSetAttribute(attn_mma_kernel,
                         cudaFuncAttributeMaxDynamicSharedMemorySize, ATTN_SMEM);

    const int n4a = MTOT * HIDDEN / 4;
    const int n4w = HIDDEN * HIDDEN / 4;

    cvt_kernel<<<(n4a + 255) / 256, 256>>>((const float4*)x,  (float4*)gat, n4a);
    cvt_kernel<<<(n4w + 255) / 256, 256>>>((const float4*)wq, (float4*)gwq, n4w);
    cvt_kernel<<<(n4w + 255) / 256, 256>>>((const float4*)wk, (float4*)gwk, n4w);
    cvt_kernel<<<(n4w + 255) / 256, 256>>>((const float4*)wv, (float4*)gwv, n4w);
    cvt_kernel<<<(n4w + 255) / 256, 256>>>((const float4*)wo, (float4*)gwo, n4w);

    {   // fused QKV projections (tensor cores)
        dim3 g(HIDDEN / BN, MTOT / BM, 3);
        gemm_mma_kernel<<<g, 256, GEMM_SMEM>>>(gat, gwq, gwk, gwv,
                                               bq, bk, bv, gq, gk, gv, 0);
    }
    {   // MMA attention, writes tf32-rounded output straight into g_At
        dim3 ga(SEQ / QB, NH, BATCH);
        attn_mma_kernel<<<ga, 256, ATTN_SMEM>>>(gq, gk, gv, gat);
    }
    {   // output projection
        dim3 g(HIDDEN / BN, MTOT / BM, 1);
        gemm_mma_kernel<<<g, 256, GEMM_SMEM>>>(gat, gwo, gwo, gwo,
                                               bo, bo, bo, (float*)d_out,
                                               (float*)d_out, (float*)d_out, 1);
    }
}

// round 5
// speedup vs baseline: 3.0201x; 1.1850x over previous
#include <cuda_runtime.h>
#include <cstdint>
#include <math.h>

#define HIDDEN 1024
#define NH     16
#define HD     64
#define SEQ    2048
#define BATCH  2
#define MTOT   (BATCH*SEQ)   // 4096
#define WIN    128
#define QB     64
#define KT     (QB + 2*WIN)  // 320

// ---------------- scratch (device globals) -------------------------------------
__device__ float g_Q[BATCH*NH*SEQ*HD];
__device__ float g_K[BATCH*NH*SEQ*HD];
__device__ float g_V[BATCH*NH*SEQ*HD];
__device__ float g_At[MTOT*HIDDEN];     // tf32-rounded activations
__device__ float g_Wq[HIDDEN*HIDDEN];
__device__ float g_Wk[HIDDEN*HIDDEN];
__device__ float g_Wv[HIDDEN*HIDDEN];
__device__ float g_Wo[HIDDEN*HIDDEN];

// ---------------- helpers -------------------------------------------------------
__device__ __forceinline__ uint32_t smem_u32(const void* p) {
    uint32_t a;
    asm("{ .reg .u64 t; cvta.to.shared.u64 t, %1; cvt.u32.u64 %0, t; }" : "=r"(a) : "l"(p));
    return a;
}
__device__ __forceinline__ float tf32r(float x) {
    uint32_t y;
    asm("cvt.rna.tf32.f32 %0, %1;" : "=r"(y) : "f"(x));
    return __uint_as_float(y);
}
__device__ __forceinline__ void cp16(uint32_t dst, const float* src) {
    asm volatile("cp.async.cg.shared.global [%0], [%1], 16;" :: "r"(dst), "l"(src) : "memory");
}
#define CP_COMMIT() asm volatile("cp.async.commit_group;" ::: "memory")
#define CP_WAIT1()  asm volatile("cp.async.wait_group 1;" ::: "memory")

__device__ __forceinline__ void mma_tf32(float* d, const uint32_t* a, const uint32_t* b) {
    asm volatile("mma.sync.aligned.m16n8k8.row.col.f32.tf32.tf32.f32 "
        "{%0,%1,%2,%3}, {%4,%5,%6,%7}, {%8,%9}, {%0,%1,%2,%3};"
        : "+f"(d[0]), "+f"(d[1]), "+f"(d[2]), "+f"(d[3])
        : "r"(a[0]), "r"(a[1]), "r"(a[2]), "r"(a[3]), "r"(b[0]), "r"(b[1]));
}

// ---------------- tf32 tensor-core GEMM: 128x256 CTA tile, 64x64 warp tile -------
#define BM 128
#define BN 256
#define BK 32
#define STAGES 3
#define AS_STRIDE 36
#define BS_STRIDE 260
#define A_STAGE (BM*AS_STRIDE)             // 4608
#define B_STAGE (BK*BS_STRIDE)             // 8320
#define STAGE_FLOATS (A_STAGE + B_STAGE)   // 12928
#define GEMM_SMEM (STAGES*STAGE_FLOATS*4)  // 155136 B

__global__ __launch_bounds__(256, 1) void gemm_mma_kernel(
    const float* __restrict__ A,
    const float* __restrict__ W0, const float* __restrict__ W1, const float* __restrict__ W2,
    const float* __restrict__ bias0, const float* __restrict__ bias1, const float* __restrict__ bias2,
    float* __restrict__ out0, float* __restrict__ out1, float* __restrict__ out2,
    int mode)
{
    extern __shared__ float sm[];
    const int tid  = threadIdx.x;
    const int lane = tid & 31;
    const int wid  = tid >> 5;
    const int n0 = blockIdx.x * BN;
    const int m0 = blockIdx.y * BM;
    const int z  = blockIdx.z;

    const float* W    = (z == 0) ? W0 : (z == 1) ? W1 : W2;
    const float* bias = (z == 0) ? bias0 : (z == 1) ? bias1 : bias2;
    float* out        = (z == 0) ? out0 : (z == 1) ? out1 : out2;

    const int wm = (wid & 1) * 64;      // 2 warp-rows
    const int wn = (wid >> 1) * 64;     // 4 warp-cols

    float d[4][8][4];
#pragma unroll
    for (int mi = 0; mi < 4; mi++)
#pragma unroll
        for (int ni = 0; ni < 8; ni++)
#pragma unroll
            for (int c = 0; c < 4; c++) d[mi][ni][c] = 0.f;

    const uint32_t sb = smem_u32(sm);

    auto load_stage = [&](int kt, int s) {
        const uint32_t a_off = sb + (uint32_t)(s * STAGE_FLOATS) * 4u;
        const uint32_t b_off = a_off + A_STAGE * 4u;
        const float* Ag = A + (long)m0 * HIDDEN + kt * BK;
        const float* Wg = W + (long)(kt * BK) * HIDDEN + n0;
#pragma unroll
        for (int rep = 0; rep < 4; rep++) {
            int lin = rep * 256 + tid;
            int ar = lin >> 3, aq = lin & 7;
            cp16(a_off + (uint32_t)(ar * AS_STRIDE + aq * 4) * 4u,
                 Ag + (long)ar * HIDDEN + aq * 4);
        }
#pragma unroll
        for (int rep = 0; rep < 8; rep++) {
            int lin = rep * 256 + tid;
            int br = lin >> 6, bq = lin & 63;
            cp16(b_off + (uint32_t)(br * BS_STRIDE + bq * 4) * 4u,
                 Wg + (long)br * HIDDEN + bq * 4);
        }
        CP_COMMIT();
    };

    load_stage(0, 0);
    load_stage(1, 1);

    const int lg = lane >> 2;
    const int lt = lane & 3;

    for (int kt = 0; kt < HIDDEN / BK; kt++) {
        const int s = kt % STAGES;
        CP_WAIT1();
        __syncthreads();
        if (kt + 2 < HIDDEN / BK) load_stage(kt + 2, (kt + 2) % STAGES);
        else CP_COMMIT();   // keep group accounting constant

        const float* As = sm + s * STAGE_FLOATS;
        const float* Bs = As + A_STAGE;

#pragma unroll
        for (int k8 = 0; k8 < 4; k8++) {
            const int kb = k8 * 8;
            uint32_t a[4][4];
#pragma unroll
            for (int mi = 0; mi < 4; mi++) {
                const float* ap = As + (wm + mi * 16 + lg) * AS_STRIDE + kb + lt;
                a[mi][0] = __float_as_uint(ap[0]);
                a[mi][1] = __float_as_uint(ap[8 * AS_STRIDE]);
                a[mi][2] = __float_as_uint(ap[4]);
                a[mi][3] = __float_as_uint(ap[8 * AS_STRIDE + 4]);
            }
#pragma unroll
            for (int ni = 0; ni < 8; ni++) {
                uint32_t bb[2];
                const float* bp = Bs + (kb + lt) * BS_STRIDE + wn + ni * 8 + lg;
                bb[0] = __float_as_uint(bp[0]);
                bb[1] = __float_as_uint(bp[4 * BS_STRIDE]);
#pragma unroll
                for (int mi = 0; mi < 4; mi++)
                    mma_tf32(d[mi][ni], a[mi], bb);
            }
        }
    }

    // ---- epilogue ----
#pragma unroll
    for (int mi = 0; mi < 4; mi++) {
#pragma unroll
        for (int rh = 0; rh < 2; rh++) {
            const int row = m0 + wm + mi * 16 + lg + rh * 8;
            const int bb = row >> 11;
            const int ss = row & (SEQ - 1);
#pragma unroll
            for (int ni = 0; ni < 8; ni++) {
                const int col = n0 + wn + ni * 8 + lt * 2;
                float2 v;
                v.x = d[mi][ni][rh * 2 + 0] + __ldg(&bias[col]);
                v.y = d[mi][ni][rh * 2 + 1] + __ldg(&bias[col + 1]);
                if (mode == 0) {
                    const int h  = col >> 6;
                    const int dd = col & 63;
                    *(float2*)&out[(((long)(bb * NH + h) * SEQ) + ss) * HD + dd] = v;
                } else {
                    *(float2*)&out[(long)row * HIDDEN + col] = v;
                }
            }
        }
    }
}

// ---------------- tf32 rounding (elementwise) ------------------------------------
__global__ void cvt_kernel(const float4* __restrict__ in, float4* __restrict__ out, int n4) {
    int i = blockIdx.x * blockDim.x + threadIdx.x;
    if (i < n4) {
        float4 v = in[i];
        v.x = tf32r(v.x); v.y = tf32r(v.y); v.z = tf32r(v.z); v.w = tf32r(v.w);
        out[i] = v;
    }
}

// ---------------- sliding-window attention via tensor-core MMA --------------------
#define SQ 68
#define SK 328
#define SV 72
#define SP 324
#define SO 66
#define QS_OFF  0
#define KP_OFF  4352
#define VS_OFF  (KP_OFF + 64*SK)
#define RED_OFF (VS_OFF + KT*SV)
#define ATTN_FLOATS (RED_OFF + 128)
#define ATTN_SMEM (ATTN_FLOATS * 4)

__global__ __launch_bounds__(256, 1) void attn_mma_kernel(
    const float* __restrict__ Q, const float* __restrict__ K,
    const float* __restrict__ V, float* __restrict__ O)
{
    extern __shared__ float sm[];
    float* Qs  = sm + QS_OFF;   // [64][68], reused as obuf [64][66]
    float* Kst = sm + KP_OFF;   // [64][328] d-major, reused as P [64][324]
    float* Vs  = sm + VS_OFF;   // [320][72]
    float* red = sm + RED_OFF;  // [2][64]

    const int q0 = blockIdx.x * QB;
    const int h  = blockIdx.y;
    const int b  = blockIdx.z;
    const int tid = threadIdx.x;
    const long base = ((long)(b * NH + h)) * SEQ * HD;
    const float* Kb = K + base;
    const float* Vb = V + base;
    const float* Qb = Q + base;
    const int j0 = q0 - WIN;

    // ---- load Q tile (rounded tf32) ----
    for (int idx = tid; idx < 64 * 16; idx += 256) {
        int r = idx >> 4, c4 = (idx & 15) << 2;
        float4 v = *(const float4*)&Qb[(long)(q0 + r) * HD + c4];
        v.x = tf32r(v.x); v.y = tf32r(v.y); v.z = tf32r(v.z); v.w = tf32r(v.w);
        *(float4*)&Qs[r * SQ + c4] = v;
    }
    // ---- load K transposed [d][key] + V [key][d], division-free decomposition ----
    {
        const int jbase = tid & 63;         // 0..63
        const int dsel  = tid >> 6;         // 0..3
#pragma unroll
        for (int r5 = 0; r5 < 5; r5++) {
            const int jj = r5 * 64 + jbase;
            const int j  = j0 + jj;
            const bool ok = (j >= 0 && j < SEQ);
#pragma unroll
            for (int q2 = 0; q2 < 4; q2++) {
                const int dq = dsel * 4 + q2 * 16;
                float4 kv = make_float4(0.f, 0.f, 0.f, 0.f);
                float4 vv = kv;
                if (ok) {
                    kv = *(const float4*)&Kb[(long)j * HD + dq];
                    vv = *(const float4*)&Vb[(long)j * HD + dq];
                }
                Kst[(dq + 0) * SK + jj] = tf32r(kv.x);
                Kst[(dq + 1) * SK + jj] = tf32r(kv.y);
                Kst[(dq + 2) * SK + jj] = tf32r(kv.z);
                Kst[(dq + 3) * SK + jj] = tf32r(kv.w);
                vv.x = tf32r(vv.x); vv.y = tf32r(vv.y); vv.z = tf32r(vv.z); vv.w = tf32r(vv.w);
                *(float4*)&Vs[jj * SV + dq] = vv;
            }
        }
    }
    __syncthreads();

    const int lane = tid & 31;
    const int wid  = tid >> 5;
    const int lg = lane >> 2;
    const int lt = lane & 3;
    const int wm = (wid & 3) * 16;
    const int wn = (wid >> 2) * 160;
    const float scale = 0.125f;

    // ---- S = Q @ K^T ----
    uint32_t a[8][4];
#pragma unroll
    for (int k8 = 0; k8 < 8; k8++) {
        const float* ap = Qs + (wm + lg) * SQ + k8 * 8 + lt;
        a[k8][0] = __float_as_uint(ap[0]);
        a[k8][1] = __float_as_uint(ap[8 * SQ]);
        a[k8][2] = __float_as_uint(ap[4]);
        a[k8][3] = __float_as_uint(ap[8 * SQ + 4]);
    }
    float c[20][4];
#pragma unroll
    for (int nt = 0; nt < 20; nt++) {
        c[nt][0] = 0.f; c[nt][1] = 0.f; c[nt][2] = 0.f; c[nt][3] = 0.f;
        const int key = wn + nt * 8 + lg;
#pragma unroll
        for (int k8 = 0; k8 < 8; k8++) {
            uint32_t bb[2];
            const float* bp = Kst + (k8 * 8 + lt) * SK + key;
            bb[0] = __float_as_uint(bp[0]);
            bb[1] = __float_as_uint(bp[4 * SK]);
            mma_tf32(c[nt], a[k8], bb);
        }
    }

    // ---- band mask + exp + row sums ----
    const int r0 = q0 + wm + lg;
    const int r1 = r0 + 8;
    const int lo0 = ((r0 - WIN > 0) ? r0 - WIN : 0) - j0;
    const int hi0 = ((r0 + WIN < SEQ - 1) ? r0 + WIN : SEQ - 1) - j0;
    const int lo1 = ((r1 - WIN > 0) ? r1 - WIN : 0) - j0;
    const int hi1 = ((r1 + WIN < SEQ - 1) ? r1 + WIN : SEQ - 1) - j0;

    float sum0 = 0.f, sum1 = 0.f;
#pragma unroll
    for (int nt = 0; nt < 20; nt++) {
        const int jj = wn + nt * 8 + 2 * lt;
        float p0 = (jj     >= lo0 && jj     <= hi0) ? tf32r(__expf(c[nt][0] * scale)) : 0.f;
        float p1 = (jj + 1 >= lo0 && jj + 1 <= hi0) ? tf32r(__expf(c[nt][1] * scale)) : 0.f;
        float p2 = (jj     >= lo1 && jj     <= hi1) ? tf32r(__expf(c[nt][2] * scale)) : 0.f;
        float p3 = (jj + 1 >= lo1 && jj + 1 <= hi1) ? tf32r(__expf(c[nt][3] * scale)) : 0.f;
        c[nt][0] = p0; c[nt][1] = p1; c[nt][2] = p2; c[nt][3] = p3;
        sum0 += p0 + p1;
        sum1 += p2 + p3;
    }
    sum0 += __shfl_xor_sync(0xffffffffu, sum0, 1);
    sum0 += __shfl_xor_sync(0xffffffffu, sum0, 2);
    sum1 += __shfl_xor_sync(0xffffffffu, sum1, 1);
    sum1 += __shfl_xor_sync(0xffffffffu, sum1, 2);

    __syncthreads();

    float* Ps = Kst;
#pragma unroll
    for (int nt = 0; nt < 20; nt++) {
        const int col = wn + nt * 8 + 2 * lt;
        *(float2*)&Ps[(wm + lg) * SP + col]     = make_float2(c[nt][0], c[nt][1]);
        *(float2*)&Ps[(wm + lg + 8) * SP + col] = make_float2(c[nt][2], c[nt][3]);
    }
    if (lt == 0) {
        red[(wid >> 2) * 64 + wm + lg]     = sum0;
        red[(wid >> 2) * 64 + wm + lg + 8] = sum1;
    }
    __syncthreads();

    // ---- O_partial = P @ V ----
    float o[8][4];
#pragma unroll
    for (int nt = 0; nt < 8; nt++) { o[nt][0] = 0.f; o[nt][1] = 0.f; o[nt][2] = 0.f; o[nt][3] = 0.f; }

#pragma unroll
    for (int k8 = 0; k8 < 20; k8++) {
        const int kk = wn + k8 * 8;
        uint32_t a2[4];
        const float* ap = Ps + (wm + lg) * SP + kk + lt;
        a2[0] = __float_as_uint(ap[0]);
        a2[1] = __float_as_uint(ap[8 * SP]);
        a2[2] = __float_as_uint(ap[4]);
        a2[3] = __float_as_uint(ap[8 * SP + 4]);
#pragma unroll
        for (int nt = 0; nt < 8; nt++) {
            uint32_t bb[2];
            const float* bp = Vs + (kk + lt) * SV + nt * 8 + lg;
            bb[0] = __float_as_uint(bp[0]);
            bb[1] = __float_as_uint(bp[4 * SV]);
            mma_tf32(o[nt], a2, bb);
        }
    }

    // ---- combine split-K halves, normalize, write tf32-rounded ----
    float* obuf = Qs;
    if ((wid >> 2) == 0) {
#pragma unroll
        for (int nt = 0; nt < 8; nt++) {
            const int col = nt * 8 + 2 * lt;
            *(float2*)&obuf[(wm + lg) * SO + col]     = make_float2(o[nt][0], o[nt][1]);
            *(float2*)&obuf[(wm + lg + 8) * SO + col] = make_float2(o[nt][2], o[nt][3]);
        }
    }
    __syncthreads();
    if ((wid >> 2) == 1) {
        const float inv0 = 1.f / (red[wm + lg] + red[64 + wm + lg]);
        const float inv1 = 1.f / (red[wm + lg + 8] + red[64 + wm + lg + 8]);
        const long ob0 = ((long)(b * SEQ + r0)) * HIDDEN + h * HD;
        const long ob1 = ((long)(b * SEQ + r1)) * HIDDEN + h * HD;
#pragma unroll
        for (int nt = 0; nt < 8; nt++) {
            const int col = nt * 8 + 2 * lt;
            float2 u0 = *(const float2*)&obuf[(wm + lg) * SO + col];
            float2 u1 = *(const float2*)&obuf[(wm + lg + 8) * SO + col];
            float2 w0, w1;
            w0.x = tf32r((o[nt][0] + u0.x) * inv0);
            w0.y = tf32r((o[nt][1] + u0.y) * inv0);
            w1.x = tf32r((o[nt][2] + u1.x) * inv1);
            w1.y = tf32r((o[nt][3] + u1.y) * inv1);
            *(float2*)&O[ob0 + col] = w0;
            *(float2*)&O[ob1 + col] = w1;
        }
    }
}

// ---------------- launcher --------------------------------------------------------
extern "C" void kernel_launch(void* const* d_in, const int* in_sizes, int n_in,
                              void* d_out, int out_size)
{
    const float* x  = (const float*)d_in[0];
    const float* wq = (const float*)d_in[1];
    const float* bq = (const float*)d_in[2];
    const float* wk = (const float*)d_in[3];
    const float* bk = (const float*)d_in[4];
    const float* wv = (const float*)d_in[5];
    const float* bv = (const float*)d_in[6];
    const float* wo = (const float*)d_in[7];
    const float* bo = (const float*)d_in[8];

    float *gq, *gk, *gv, *gat, *gwq, *gwk, *gwv, *gwo;
    cudaGetSymbolAddress((void**)&gq,  g_Q);
    cudaGetSymbolAddress((void**)&gk,  g_K);
    cudaGetSymbolAddress((void**)&gv,  g_V);
    cudaGetSymbolAddress((void**)&gat, g_At);
    cudaGetSymbolAddress((void**)&gwq, g_Wq);
    cudaGetSymbolAddress((void**)&gwk, g_Wk);
    cudaGetSymbolAddress((void**)&gwv, g_Wv);
    cudaGetSymbolAddress((void**)&gwo, g_Wo);

    cudaFuncSetAttribute(gemm_mma_kernel,
                         cudaFuncAttributeMaxDynamicSharedMemorySize, GEMM_SMEM);
    cudaFuncSetAttribute(attn_mma_kernel,
                         cudaFuncAttributeMaxDynamicSharedMemorySize, ATTN_SMEM);

    const int n4a = MTOT * HIDDEN / 4;
    const int n4w = HIDDEN * HIDDEN / 4;

    cvt_kernel<<<(n4a + 255) / 256, 256>>>((const float4*)x,  (float4*)gat, n4a);
    cvt_kernel<<<(n4w + 255) / 256, 256>>>((const float4*)wq, (float4*)gwq, n4w);
    cvt_kernel<<<(n4w + 255) / 256, 256>>>((const float4*)wk, (float4*)gwk, n4w);
    cvt_kernel<<<(n4w + 255) / 256, 256>>>((const float4*)wv, (float4*)gwv, n4w);
    cvt_kernel<<<(n4w + 255) / 256, 256>>>((const float4*)wo, (float4*)gwo, n4w);

    {   // fused QKV projections
        dim3 g(HIDDEN / BN, MTOT / BM, 3);
        gemm_mma_kernel<<<g, 256, GEMM_SMEM>>>(gat, gwq, gwk, gwv,
                                               bq, bk, bv, gq, gk, gv, 0);
    }
    {   // MMA attention -> writes tf32-rounded into g_At
        dim3 ga(SEQ / QB, NH, BATCH);
        attn_mma_kernel<<<ga, 256, ATTN_SMEM>>>(gq, gk, gv, gat);
    }
    {   // output projection
        dim3 g(HIDDEN / BN, MTOT / BM, 1);
        gemm_mma_kernel<<<g, 256, GEMM_SMEM>>>(gat, gwo, gwo, gwo,
                                               bo, bo, bo, (float*)d_out,
                                               (float*)d_out, (float*)d_out, 1);
    }
}

// round 6
// speedup vs baseline: 3.4588x; 1.1452x over previous
#include <cuda_runtime.h>
#include <cstdint>
#include <math.h>

#define HIDDEN 1024
#define NH     16
#define HD     64
#define SEQ    2048
#define BATCH  2
#define MTOT   (BATCH*SEQ)   // 4096
#define WIN    128
#define QB     64
#define KT     (QB + 2*WIN)  // 320

// ---------------- scratch (device globals) -------------------------------------
__device__ float g_Q[BATCH*NH*SEQ*HD];
__device__ float g_K[BATCH*NH*SEQ*HD];
__device__ float g_V[BATCH*NH*SEQ*HD];
__device__ float g_At[MTOT*HIDDEN];
__device__ float g_Wq[HIDDEN*HIDDEN];
__device__ float g_Wk[HIDDEN*HIDDEN];
__device__ float g_Wv[HIDDEN*HIDDEN];
__device__ float g_Wo[HIDDEN*HIDDEN];

// ---------------- helpers -------------------------------------------------------
__device__ __forceinline__ uint32_t smem_u32(const void* p) {
    uint32_t a;
    asm("{ .reg .u64 t; cvta.to.shared.u64 t, %1; cvt.u32.u64 %0, t; }" : "=r"(a) : "l"(p));
    return a;
}
__device__ __forceinline__ float tf32r(float x) {
    uint32_t y;
    asm("cvt.rna.tf32.f32 %0, %1;" : "=r"(y) : "f"(x));
    return __uint_as_float(y);
}
__device__ __forceinline__ void cp16(uint32_t dst, const float* src) {
    asm volatile("cp.async.cg.shared.global [%0], [%1], 16;" :: "r"(dst), "l"(src) : "memory");
}
__device__ __forceinline__ void cp16z(uint32_t dst, const float* src, int srcsz) {
    asm volatile("cp.async.cg.shared.global [%0], [%1], 16, %2;"
                 :: "r"(dst), "l"(src), "r"(srcsz) : "memory");
}
#define CP_COMMIT() asm volatile("cp.async.commit_group;" ::: "memory")
#define CP_WAIT1()  asm volatile("cp.async.wait_group 1;" ::: "memory")
#define CP_WAIT0()  asm volatile("cp.async.wait_group 0;" ::: "memory")

__device__ __forceinline__ void mma_tf32(float* d, const uint32_t* a, const uint32_t* b) {
    asm volatile("mma.sync.aligned.m16n8k8.row.col.f32.tf32.tf32.f32 "
        "{%0,%1,%2,%3}, {%4,%5,%6,%7}, {%8,%9}, {%0,%1,%2,%3};"
        : "+f"(d[0]), "+f"(d[1]), "+f"(d[2]), "+f"(d[3])
        : "r"(a[0]), "r"(a[1]), "r"(a[2]), "r"(a[3]), "r"(b[0]), "r"(b[1]));
}

// ---------------- tf32 tensor-core GEMM: 128x256 CTA tile (unchanged R5) ---------
#define BM 128
#define BN 256
#define BK 32
#define STAGES 3
#define AS_STRIDE 36
#define BS_STRIDE 260
#define A_STAGE (BM*AS_STRIDE)
#define B_STAGE (BK*BS_STRIDE)
#define STAGE_FLOATS (A_STAGE + B_STAGE)
#define GEMM_SMEM (STAGES*STAGE_FLOATS*4)

__global__ __launch_bounds__(256, 1) void gemm_mma_kernel(
    const float* __restrict__ A,
    const float* __restrict__ W0, const float* __restrict__ W1, const float* __restrict__ W2,
    const float* __restrict__ bias0, const float* __restrict__ bias1, const float* __restrict__ bias2,
    float* __restrict__ out0, float* __restrict__ out1, float* __restrict__ out2,
    int mode)
{
    extern __shared__ float sm[];
    const int tid  = threadIdx.x;
    const int lane = tid & 31;
    const int wid  = tid >> 5;
    const int n0 = blockIdx.x * BN;
    const int m0 = blockIdx.y * BM;
    const int z  = blockIdx.z;

    const float* W    = (z == 0) ? W0 : (z == 1) ? W1 : W2;
    const float* bias = (z == 0) ? bias0 : (z == 1) ? bias1 : bias2;
    float* out        = (z == 0) ? out0 : (z == 1) ? out1 : out2;

    const int wm = (wid & 1) * 64;
    const int wn = (wid >> 1) * 64;

    float d[4][8][4];
#pragma unroll
    for (int mi = 0; mi < 4; mi++)
#pragma unroll
        for (int ni = 0; ni < 8; ni++)
#pragma unroll
            for (int c = 0; c < 4; c++) d[mi][ni][c] = 0.f;

    const uint32_t sb = smem_u32(sm);

    auto load_stage = [&](int kt, int s) {
        const uint32_t a_off = sb + (uint32_t)(s * STAGE_FLOATS) * 4u;
        const uint32_t b_off = a_off + A_STAGE * 4u;
        const float* Ag = A + (long)m0 * HIDDEN + kt * BK;
        const float* Wg = W + (long)(kt * BK) * HIDDEN + n0;
#pragma unroll
        for (int rep = 0; rep < 4; rep++) {
            int lin = rep * 256 + tid;
            int ar = lin >> 3, aq = lin & 7;
            cp16(a_off + (uint32_t)(ar * AS_STRIDE + aq * 4) * 4u,
                 Ag + (long)ar * HIDDEN + aq * 4);
        }
#pragma unroll
        for (int rep = 0; rep < 8; rep++) {
            int lin = rep * 256 + tid;
            int br = lin >> 6, bq = lin & 63;
            cp16(b_off + (uint32_t)(br * BS_STRIDE + bq * 4) * 4u,
                 Wg + (long)br * HIDDEN + bq * 4);
        }
        CP_COMMIT();
    };

    load_stage(0, 0);
    load_stage(1, 1);

    const int lg = lane >> 2;
    const int lt = lane & 3;

    for (int kt = 0; kt < HIDDEN / BK; kt++) {
        const int s = kt % STAGES;
        CP_WAIT1();
        __syncthreads();
        if (kt + 2 < HIDDEN / BK) load_stage(kt + 2, (kt + 2) % STAGES);
        else CP_COMMIT();

        const float* As = sm + s * STAGE_FLOATS;
        const float* Bs = As + A_STAGE;

#pragma unroll
        for (int k8 = 0; k8 < 4; k8++) {
            const int kb = k8 * 8;
            uint32_t a[4][4];
#pragma unroll
            for (int mi = 0; mi < 4; mi++) {
                const float* ap = As + (wm + mi * 16 + lg) * AS_STRIDE + kb + lt;
                a[mi][0] = __float_as_uint(ap[0]);
                a[mi][1] = __float_as_uint(ap[8 * AS_STRIDE]);
                a[mi][2] = __float_as_uint(ap[4]);
                a[mi][3] = __float_as_uint(ap[8 * AS_STRIDE + 4]);
            }
#pragma unroll
            for (int ni = 0; ni < 8; ni++) {
                uint32_t bb[2];
                const float* bp = Bs + (kb + lt) * BS_STRIDE + wn + ni * 8 + lg;
                bb[0] = __float_as_uint(bp[0]);
                bb[1] = __float_as_uint(bp[4 * BS_STRIDE]);
#pragma unroll
                for (int mi = 0; mi < 4; mi++)
                    mma_tf32(d[mi][ni], a[mi], bb);
            }
        }
    }

#pragma unroll
    for (int mi = 0; mi < 4; mi++) {
#pragma unroll
        for (int rh = 0; rh < 2; rh++) {
            const int row = m0 + wm + mi * 16 + lg + rh * 8;
            const int bb = row >> 11;
            const int ss = row & (SEQ - 1);
#pragma unroll
            for (int ni = 0; ni < 8; ni++) {
                const int col = n0 + wn + ni * 8 + lt * 2;
                float2 v;
                v.x = d[mi][ni][rh * 2 + 0] + __ldg(&bias[col]);
                v.y = d[mi][ni][rh * 2 + 1] + __ldg(&bias[col + 1]);
                if (mode == 0) {
                    const int h  = col >> 6;
                    const int dd = col & 63;
                    *(float2*)&out[(((long)(bb * NH + h) * SEQ) + ss) * HD + dd] = v;
                } else {
                    *(float2*)&out[(long)row * HIDDEN + col] = v;
                }
            }
        }
    }
}

// ---------------- tf32 rounding ---------------------------------------------------
__global__ void cvt_kernel(const float4* __restrict__ in, float4* __restrict__ out, int n4) {
    int i = blockIdx.x * blockDim.x + threadIdx.x;
    if (i < n4) {
        float4 v = in[i];
        v.x = tf32r(v.x); v.y = tf32r(v.y); v.z = tf32r(v.z); v.w = tf32r(v.w);
        out[i] = v;
    }
}
// all 4 weights in one launch (z selects tensor)
__global__ void cvtw_kernel(const float4* __restrict__ w0, const float4* __restrict__ w1,
                            const float4* __restrict__ w2, const float4* __restrict__ w3,
                            float4* __restrict__ o0, float4* __restrict__ o1,
                            float4* __restrict__ o2, float4* __restrict__ o3) {
    const int z = blockIdx.y;
    const float4* in = (z == 0) ? w0 : (z == 1) ? w1 : (z == 2) ? w2 : w3;
    float4* out      = (z == 0) ? o0 : (z == 1) ? o1 : (z == 2) ? o2 : o3;
    int i = blockIdx.x * blockDim.x + threadIdx.x;
    float4 v = in[i];
    v.x = tf32r(v.x); v.y = tf32r(v.y); v.z = tf32r(v.z); v.w = tf32r(v.w);
    out[i] = v;
}

// ---------------- chunked sliding-window attention (2 CTAs/SM) --------------------
#define CH   160
#define SQ   68
#define SKC  168
#define SVC  72
#define SPC  164
#define SO   66
#define QS_OFF  0
#define KP_OFF  4352                       // Qs: 64*68
#define VS_OFF  (KP_OFF + 64*SKC)          // 15104
#define RED_OFF (VS_OFF + CH*SVC)          // 26624
#define ATTN_FLOATS (RED_OFF + 128)        // 26752
#define ATTN_SMEM (ATTN_FLOATS * 4)        // 107008 B

__global__ __launch_bounds__(256, 2) void attn_mma_kernel(
    const float* __restrict__ Q, const float* __restrict__ K,
    const float* __restrict__ V, float* __restrict__ O)
{
    extern __shared__ float sm[];
    float* Qs  = sm + QS_OFF;   // [64][68]; later obuf [64][66]
    float* Kst = sm + KP_OFF;   // [64][168] d-major; aliased by P [64][164]
    float* Vs  = sm + VS_OFF;   // [160][72]
    float* red = sm + RED_OFF;  // [2][64]

    const int q0 = blockIdx.x * QB;
    const int h  = blockIdx.y;
    const int b  = blockIdx.z;
    const int tid = threadIdx.x;
    const long base = ((long)(b * NH + h)) * SEQ * HD;
    const float* Kb = K + base;
    const float* Vb = V + base;
    const float* Qb = Q + base;
    const int j0 = q0 - WIN;

    const uint32_t sb = smem_u32(sm);
    const int lane = tid & 31;
    const int wid  = tid >> 5;
    const int lg = lane >> 2;
    const int lt = lane & 3;
    const int wm = (wid & 3) * 16;     // query tile
    const int half = wid >> 2;         // key half within chunk
    const int wn = half * 80;
    const float scale = 0.125f;

    // ---- load Q tile (tf32 rna) ----
    for (int idx = tid; idx < 64 * 16; idx += 256) {
        int r = idx >> 4, c4 = (idx & 15) << 2;
        float4 v = *(const float4*)&Qb[(long)(q0 + r) * HD + c4];
        v.x = tf32r(v.x); v.y = tf32r(v.y); v.z = tf32r(v.z); v.w = tf32r(v.w);
        *(float4*)&Qs[r * SQ + c4] = v;
    }

    // persistent accumulators
    float o[8][4];
#pragma unroll
    for (int nt = 0; nt < 8; nt++) { o[nt][0] = 0.f; o[nt][1] = 0.f; o[nt][2] = 0.f; o[nt][3] = 0.f; }
    float sum0 = 0.f, sum1 = 0.f;

    const int r0 = q0 + wm + lg;
    const int r1 = r0 + 8;
    const int lo0 = ((r0 - WIN > 0) ? r0 - WIN : 0) - j0;
    const int hi0 = ((r0 + WIN < SEQ - 1) ? r0 + WIN : SEQ - 1) - j0;
    const int lo1 = ((r1 - WIN > 0) ? r1 - WIN : 0) - j0;
    const int hi1 = ((r1 + WIN < SEQ - 1) ? r1 + WIN : SEQ - 1) - j0;

    uint32_t a[8][4];
    bool afrag_loaded = false;

#pragma unroll
    for (int ch = 0; ch < 2; ch++) {
        const int cb = ch * CH;   // chunk base in window coords

        // ---- load K chunk transposed (tf32 rna): thread -> (dgrp, 5 keys) ----
        {
            const int jb   = tid & 31;        // key mod 32
            const int dgrp = tid >> 5;        // 0..7 -> dims dgrp*8..+7
#pragma unroll
            for (int r5 = 0; r5 < 5; r5++) {
                const int jj = r5 * 32 + jb;
                const int j  = j0 + cb + jj;
                const bool ok = (j >= 0 && j < SEQ);
#pragma unroll
                for (int q2 = 0; q2 < 2; q2++) {
                    const int dq = dgrp * 8 + q2 * 4;
                    float4 kv = make_float4(0.f, 0.f, 0.f, 0.f);
                    if (ok) kv = *(const float4*)&Kb[(long)j * HD + dq];
                    Kst[(dq + 0) * SKC + jj] = tf32r(kv.x);
                    Kst[(dq + 1) * SKC + jj] = tf32r(kv.y);
                    Kst[(dq + 2) * SKC + jj] = tf32r(kv.z);
                    Kst[(dq + 3) * SKC + jj] = tf32r(kv.w);
                }
            }
        }
        // ---- load V chunk via cp.async (zero-fill OOB; rz truncation in mma) ----
        {
            const int rb = tid >> 4;          // 0..15
            const int cq = (tid & 15) << 2;   // col quad
#pragma unroll
            for (int r10 = 0; r10 < 10; r10++) {
                const int jj = r10 * 16 + rb;
                const int j  = j0 + cb + jj;
                const int ok = (j >= 0 && j < SEQ) ? 16 : 0;
                cp16z(sb + (uint32_t)(VS_OFF + jj * SVC + cq) * 4u,
                      Vb + (long)j * HD + cq, ok);
            }
            CP_COMMIT();
        }
        CP_WAIT0();
        __syncthreads();

        if (!afrag_loaded) {
            afrag_loaded = true;
#pragma unroll
            for (int k8 = 0; k8 < 8; k8++) {
                const float* ap = Qs + (wm + lg) * SQ + k8 * 8 + lt;
                a[k8][0] = __float_as_uint(ap[0]);
                a[k8][1] = __float_as_uint(ap[8 * SQ]);
                a[k8][2] = __float_as_uint(ap[4]);
                a[k8][3] = __float_as_uint(ap[8 * SQ + 4]);
            }
        }

        // ---- S = Q @ K_chunk^T : m16 x n80 x k64 ----
        float c[10][4];
#pragma unroll
        for (int nt = 0; nt < 10; nt++) {
            c[nt][0] = 0.f; c[nt][1] = 0.f; c[nt][2] = 0.f; c[nt][3] = 0.f;
            const int key = wn + nt * 8 + lg;
#pragma unroll
            for (int k8 = 0; k8 < 8; k8++) {
                uint32_t bb[2];
                const float* bp = Kst + (k8 * 8 + lt) * SKC + key;
                bb[0] = __float_as_uint(bp[0]);
                bb[1] = __float_as_uint(bp[4 * SKC]);
                mma_tf32(c[nt], a[k8], bb);
            }
        }

        // ---- mask + exp + partial sums ----
#pragma unroll
        for (int nt = 0; nt < 10; nt++) {
            const int jw = cb + wn + nt * 8 + 2 * lt;
            float p0 = (jw     >= lo0 && jw     <= hi0) ? tf32r(__expf(c[nt][0] * scale)) : 0.f;
            float p1 = (jw + 1 >= lo0 && jw + 1 <= hi0) ? tf32r(__expf(c[nt][1] * scale)) : 0.f;
            float p2 = (jw     >= lo1 && jw     <= hi1) ? tf32r(__expf(c[nt][2] * scale)) : 0.f;
            float p3 = (jw + 1 >= lo1 && jw + 1 <= hi1) ? tf32r(__expf(c[nt][3] * scale)) : 0.f;
            c[nt][0] = p0; c[nt][1] = p1; c[nt][2] = p2; c[nt][3] = p3;
            sum0 += p0 + p1;
            sum1 += p2 + p3;
        }

        __syncthreads();   // all warps done reading Kst -> safe to overwrite with P

        float* Ps = Kst;
#pragma unroll
        for (int nt = 0; nt < 10; nt++) {
            const int col = wn + nt * 8 + 2 * lt;
            *(float2*)&Ps[(wm + lg) * SPC + col]     = make_float2(c[nt][0], c[nt][1]);
            *(float2*)&Ps[(wm + lg + 8) * SPC + col] = make_float2(c[nt][2], c[nt][3]);
        }
        __syncthreads();

        // ---- O += P_chunk @ V_chunk : split-K halves of 80 ----
#pragma unroll
        for (int k8 = 0; k8 < 10; k8++) {
            const int kk = wn + k8 * 8;
            uint32_t a2[4];
            const float* ap = Ps + (wm + lg) * SPC + kk + lt;
            a2[0] = __float_as_uint(ap[0]);
            a2[1] = __float_as_uint(ap[8 * SPC]);
            a2[2] = __float_as_uint(ap[4]);
            a2[3] = __float_as_uint(ap[8 * SPC + 4]);
#pragma unroll
            for (int nt = 0; nt < 8; nt++) {
                uint32_t bb[2];
                const float* bp = Vs + (kk + lt) * SVC + nt * 8 + lg;
                bb[0] = __float_as_uint(bp[0]);
                bb[1] = __float_as_uint(bp[4 * SVC]);
                mma_tf32(o[nt], a2, bb);
            }
        }
        __syncthreads();   // done reading P & V before next chunk load overwrites
    }

    // ---- reduce sums over lt, publish, combine halves, normalize, write ----
    sum0 += __shfl_xor_sync(0xffffffffu, sum0, 1);
    sum0 += __shfl_xor_sync(0xffffffffu, sum0, 2);
    sum1 += __shfl_xor_sync(0xffffffffu, sum1, 1);
    sum1 += __shfl_xor_sync(0xffffffffu, sum1, 2);
    if (lt == 0) {
        red[half * 64 + wm + lg]     = sum0;
        red[half * 64 + wm + lg + 8] = sum1;
    }

    float* obuf = Qs;   // Q no longer needed
    if (half == 0) {
#pragma unroll
        for (int nt = 0; nt < 8; nt++) {
            const int col = nt * 8 + 2 * lt;
            *(float2*)&obuf[(wm + lg) * SO + col]     = make_float2(o[nt][0], o[nt][1]);
            *(float2*)&obuf[(wm + lg + 8) * SO + col] = make_float2(o[nt][2], o[nt][3]);
        }
    }
    __syncthreads();
    if (half == 1) {
        const float inv0 = 1.f / (red[wm + lg] + red[64 + wm + lg]);
        const float inv1 = 1.f / (red[wm + lg + 8] + red[64 + wm + lg + 8]);
        const long ob0 = ((long)(b * SEQ + r0)) * HIDDEN + h * HD;
        const long ob1 = ((long)(b * SEQ + r1)) * HIDDEN + h * HD;
#pragma unroll
        for (int nt = 0; nt < 8; nt++) {
            const int col = nt * 8 + 2 * lt;
            float2 u0 = *(const float2*)&obuf[(wm + lg) * SO + col];
            float2 u1 = *(const float2*)&obuf[(wm + lg + 8) * SO + col];
            float2 w0, w1;
            w0.x = tf32r((o[nt][0] + u0.x) * inv0);
            w0.y = tf32r((o[nt][1] + u0.y) * inv0);
            w1.x = tf32r((o[nt][2] + u1.x) * inv1);
            w1.y = tf32r((o[nt][3] + u1.y) * inv1);
            *(float2*)&O[ob0 + col] = w0;
            *(float2*)&O[ob1 + col] = w1;
        }
    }
}

// ---------------- launcher --------------------------------------------------------
extern "C" void kernel_launch(void* const* d_in, const int* in_sizes, int n_in,
                              void* d_out, int out_size)
{
    const float* x  = (const float*)d_in[0];
    const float* wq = (const float*)d_in[1];
    const float* bq = (const float*)d_in[2];
    const float* wk = (const float*)d_in[3];
    const float* bk = (const float*)d_in[4];
    const float* wv = (const float*)d_in[5];
    const float* bv = (const float*)d_in[6];
    const float* wo = (const float*)d_in[7];
    const float* bo = (const float*)d_in[8];

    float *gq, *gk, *gv, *gat, *gwq, *gwk, *gwv, *gwo;
    cudaGetSymbolAddress((void**)&gq,  g_Q);
    cudaGetSymbolAddress((void**)&gk,  g_K);
    cudaGetSymbolAddress((void**)&gv,  g_V);
    cudaGetSymbolAddress((void**)&gat, g_At);
    cudaGetSymbolAddress((void**)&gwq, g_Wq);
    cudaGetSymbolAddress((void**)&gwk, g_Wk);
    cudaGetSymbolAddress((void**)&gwv, g_Wv);
    cudaGetSymbolAddress((void**)&gwo, g_Wo);

    cudaFuncSetAttribute(gemm_mma_kernel,
                         cudaFuncAttributeMaxDynamicSharedMemorySize, GEMM_SMEM);
    cudaFuncSetAttribute(attn_mma_kernel,
                         cudaFuncAttributeMaxDynamicSharedMemorySize, ATTN_SMEM);

    const int n4a = MTOT * HIDDEN / 4;
    const int n4w = HIDDEN * HIDDEN / 4;

    cvt_kernel<<<(n4a + 255) / 256, 256>>>((const float4*)x, (float4*)gat, n4a);
    {
        dim3 g(n4w / 256, 4);
        cvtw_kernel<<<g, 256>>>((const float4*)wq, (const float4*)wk,
                                (const float4*)wv, (const float4*)wo,
                                (float4*)gwq, (float4*)gwk, (float4*)gwv, (float4*)gwo);
    }
    {   // fused QKV projections
        dim3 g(HIDDEN / BN, MTOT / BM, 3);
        gemm_mma_kernel<<<g, 256, GEMM_SMEM>>>(gat, gwq, gwk, gwv,
                                               bq, bk, bv, gq, gk, gv, 0);
    }
    {   // chunked MMA attention -> tf32-rounded output into g_At
        dim3 ga(SEQ / QB, NH, BATCH);
        attn_mma_kernel<<<ga, 256, ATTN_SMEM>>>(gq, gk, gv, gat);
    }
    {   // output projection
        dim3 g(HIDDEN / BN, MTOT / BM, 1);
        gemm_mma_kernel<<<g, 256, GEMM_SMEM>>>(gat, gwo, gwo, gwo,
                                               bo, bo, bo, (float*)d_out,
                                               (float*)d_out, (float*)d_out, 1);
    }
}